// round 14
// baseline (speedup 1.0000x reference)
#include <cuda_runtime.h>
#include <cstdint>
#include <math.h>
#include <math_constants.h>

#define BSZ      16
#define SEQ      12
#define NODES    512
#define DM       256
#define NH       8
#define DH       32
#define NL       2
#define KK       16
#define DFF      1024
#define NT       (BSZ * NODES)        // 8192 decoder tokens / sequences
#define ET       (NT * KK)            // 131072 encoder tokens
#define DD       (DM * DM)            // 65536

// ------------------------- scratch (device globals; no cudaMalloc allowed) ---
__device__ float g_src[ET * DM];
__device__ float g_qkv[3L * ET * DM];          // q | k | v contiguous (fp32)
__device__ float g_tgt[NT * DM];
__device__ float g_tq [NT * DM];
__device__ float g_wc [DM * DM];
__device__ float g_hf [ET * (long)DFF];        // fp32 FFN1 output (and th)
__device__ int   g_idx[NODES * KK];

// activation digits + per-row scales
__device__ int8_t g_y1 [ET * DM];  __device__ int8_t g_y2 [ET * DM];  __device__ float g_sy [ET];
__device__ int8_t g_ao1[ET * DM];  __device__ int8_t g_ao2[ET * DM];  __device__ float g_sao[ET];
__device__ int8_t g_h1 [ET * (long)DFF]; __device__ int8_t g_h2 [ET * (long)DFF]; __device__ float g_sh [ET];
__device__ int8_t g_m1 [ET * DM];  __device__ int8_t g_m2 [ET * DM];  __device__ float g_sm [ET];
// weight digits (transposed [N,K]) + per-N-row scales
__device__ int8_t g_we1 [8 * DD];         __device__ int8_t g_we2 [8 * DD];         __device__ float g_swe [8 * DM];
__device__ int8_t g_wf11[2 * DM * DFF];   __device__ int8_t g_wf12[2 * DM * DFF];   __device__ float g_swf1[2 * DFF];
__device__ int8_t g_wf21[2 * DM * DFF];   __device__ int8_t g_wf22[2 * DM * DFF];   __device__ float g_swf2[2 * DM];
__device__ int8_t g_wx1 [8 * DD];         __device__ int8_t g_wx2 [8 * DD];         __device__ float g_swx [8 * DM];
__device__ int8_t g_wg11[2 * DM * DFF];   __device__ int8_t g_wg12[2 * DM * DFF];   __device__ float g_swg1[2 * DFF];
__device__ int8_t g_wg21[2 * DM * DFF];   __device__ int8_t g_wg22[2 * DM * DFF];   __device__ float g_swg2[2 * DM];
__device__ int8_t g_wc1 [DD];             __device__ int8_t g_wc2 [DD];             __device__ float g_swc [DM];

// ------------------------------------------------------------- helpers -------
__device__ __forceinline__ uint32_t smem_u32(const void* p) {
    uint32_t a;
    asm("{ .reg .u64 t; cvta.to.shared.u64 t, %1; cvt.u32.u64 %0, t; }" : "=r"(a) : "l"(p));
    return a;
}
__device__ __forceinline__ void cp16(uint32_t dst, const void* src) {
    asm volatile("cp.async.cg.shared.global [%0], [%1], 16;" :: "r"(dst), "l"(src) : "memory");
}
__device__ __forceinline__ void ldsm4(uint32_t* r, uint32_t addr) {
    asm volatile("ldmatrix.sync.aligned.m8n8.x4.shared.b16 {%0,%1,%2,%3}, [%4];"
        : "=r"(r[0]), "=r"(r[1]), "=r"(r[2]), "=r"(r[3]) : "r"(addr));
}
__device__ __forceinline__ void imma16832(int* c, const uint32_t* a, uint32_t b0, uint32_t b1) {
    asm volatile("mma.sync.aligned.m16n8k32.row.col.s32.s8.s8.s32 "
        "{%0,%1,%2,%3}, {%4,%5,%6,%7}, {%8,%9}, {%0,%1,%2,%3};"
        : "+r"(c[0]), "+r"(c[1]), "+r"(c[2]), "+r"(c[3])
        : "r"(a[0]), "r"(a[1]), "r"(a[2]), "r"(a[3]), "r"(b0), "r"(b1));
}
// 14-bit double-int8 quantization: q = round(v/δ), A1 = round(q/128), A2 = q-128*A1
__device__ __forceinline__ void quant2(float v, float inv, int8_t* d1, int8_t* d2) {
    float qf = rintf(v * inv);
    float a1 = rintf(qf * 0.0078125f);
    float a2 = qf - 128.f * a1;
    *d1 = (int8_t)(int)a1;
    *d2 = (int8_t)(int)a2;
}

// ------------------------------------------------------------------ top-K ----
__global__ void topk_kernel(const float* __restrict__ A, int* __restrict__ idx) {
    int n = blockIdx.x;
    __shared__ float sv[512];
    __shared__ float rv[256];
    __shared__ int   ri[256];
    int t = threadIdx.x;
    sv[t]       = A[n * 512 + t];
    sv[t + 256] = A[n * 512 + t + 256];
    __syncthreads();
    for (int it = 0; it < KK; it++) {
        float best = sv[t]; int bi = t;
        float v2 = sv[t + 256];
        if (v2 > best) { best = v2; bi = t + 256; }
        rv[t] = best; ri[t] = bi;
        __syncthreads();
        for (int s = 128; s > 0; s >>= 1) {
            if (t < s) {
                if (rv[t + s] > rv[t] || (rv[t + s] == rv[t] && ri[t + s] < ri[t])) {
                    rv[t] = rv[t + s]; ri[t] = ri[t + s];
                }
            }
            __syncthreads();
        }
        if (t == 0) { idx[n * KK + it] = ri[0]; sv[ri[0]] = -CUDART_INF_F; }
        __syncthreads();
    }
}

// ------------------------------------------------------ positional encoding --
__device__ __forceinline__ float pe_val(int p, int d) {
    int i2 = d & ~1;
    float div = expf(-(float)i2 * (9.210340371976184f / 256.f));
    float ang = (float)p * div;
    return (d & 1) ? cosf(ang) : sinf(ang);
}

// -------------------------------------------------------------- embeddings ---
__global__ void embed_src_kernel(const float* __restrict__ xc,
                                 const int* __restrict__ idx,
                                 const float* __restrict__ Wsrc,
                                 float* __restrict__ src) {
    int seq = blockIdx.x;
    int b = seq >> 9, n = seq & 511;
    __shared__ float Ws[SEQ * DM];
    __shared__ float xv[KK * SEQ];
    int t = threadIdx.x;
    for (int i = t; i < SEQ * DM; i += 256) Ws[i] = Wsrc[i];
    if (t < KK * SEQ) {
        int j = t / SEQ, s = t % SEQ;
        int node = idx[n * KK + j];
        xv[t] = xc[(b * SEQ + s) * NODES + node];
    }
    __syncthreads();
    for (int j = 0; j < KK; j++) {
        float acc = 0.f;
        #pragma unroll
        for (int s = 0; s < SEQ; s++) acc += xv[j * SEQ + s] * Ws[s * DM + t];
        src[(seq * KK + j) * DM + t] = acc * 16.f + pe_val(j, t);
    }
}

__global__ void embed_tgt_kernel(const float* __restrict__ xc,
                                 const float* __restrict__ Wtgt,
                                 float* __restrict__ tgt) {
    int seq = blockIdx.x;
    int b = seq >> 9, n = seq & 511;
    __shared__ float xv[SEQ];
    int t = threadIdx.x;
    if (t < SEQ) xv[t] = xc[(b * SEQ + t) * NODES + n];
    __syncthreads();
    float acc = 0.f;
    #pragma unroll
    for (int s = 0; s < SEQ; s++) acc += xv[s] * Wtgt[s * DM + t];
    tgt[seq * DM + t] = acc * 16.f + ((t & 1) ? 1.f : 0.f);
}

// ---------------------------------------- layernorm -> int8 digits -----------
__global__ void ln_kernel(const float* __restrict__ X, int8_t* __restrict__ Y1,
                          int8_t* __restrict__ Y2, float* __restrict__ S, int rows) {
    int row = blockIdx.x * 8 + (threadIdx.x >> 5);
    if (row >= rows) return;
    int lane = threadIdx.x & 31;
    const float* x = X + (long)row * DM;
    float vals[8];
    float s = 0.f;
    #pragma unroll
    for (int i = 0; i < 8; i++) { vals[i] = x[lane + i * 32]; s += vals[i]; }
    #pragma unroll
    for (int o = 16; o > 0; o >>= 1) s += __shfl_xor_sync(0xffffffffu, s, o);
    float mean = s * (1.f / 256.f);
    float s2 = 0.f;
    #pragma unroll
    for (int i = 0; i < 8; i++) { float d = vals[i] - mean; s2 += d * d; }
    #pragma unroll
    for (int o = 16; o > 0; o >>= 1) s2 += __shfl_xor_sync(0xffffffffu, s2, o);
    float rstd = rsqrtf(s2 * (1.f / 256.f) + 1e-6f);
    float v[8], rmax = 0.f;
    #pragma unroll
    for (int i = 0; i < 8; i++) { v[i] = (vals[i] - mean) * rstd; rmax = fmaxf(rmax, fabsf(v[i])); }
    #pragma unroll
    for (int o = 16; o > 0; o >>= 1) rmax = fmaxf(rmax, __shfl_xor_sync(0xffffffffu, rmax, o));
    rmax = fmaxf(rmax, 1e-20f);
    float inv = 16256.f / rmax;
    int8_t* y1 = Y1 + (long)row * DM;
    int8_t* y2 = Y2 + (long)row * DM;
    #pragma unroll
    for (int i = 0; i < 8; i++) {
        int8_t d1, d2; quant2(v[i], inv, &d1, &d2);
        y1[lane + i * 32] = d1;
        y2[lane + i * 32] = d2;
    }
    if (lane == 0) S[row] = rmax * (1.f / 16256.f);
}

// --------------------------- quantize rows of fp32 matrix (row-major) --------
__global__ void quant_rows(const float* __restrict__ X, int8_t* __restrict__ D1,
                           int8_t* __restrict__ D2, float* __restrict__ S, int C) {
    long row = blockIdx.x;
    int t = threadIdx.x;
    int per = C >> 8;
    const float* x = X + row * C;
    float v[4], m = 0.f;
    for (int j = 0; j < per; j++) { v[j] = x[t + j * 256]; m = fmaxf(m, fabsf(v[j])); }
    #pragma unroll
    for (int o = 16; o > 0; o >>= 1) m = fmaxf(m, __shfl_xor_sync(0xffffffffu, m, o));
    __shared__ float red[8];
    __shared__ float binv;
    if ((t & 31) == 0) red[t >> 5] = m;
    __syncthreads();
    if (t == 0) {
        float mm = red[0];
        #pragma unroll
        for (int j = 1; j < 8; j++) mm = fmaxf(mm, red[j]);
        mm = fmaxf(mm, 1e-20f);
        binv = 16256.f / mm;
        S[row] = mm * (1.f / 16256.f);
    }
    __syncthreads();
    float inv = binv;
    for (int j = 0; j < per; j++) {
        int8_t d1, d2; quant2(v[j], inv, &d1, &d2);
        D1[row * C + t + j * 256] = d1;
        D2[row * C + t + j * 256] = d2;
    }
}

// -------------- transpose + quantize weight columns: W[K,N] -> digits[N,K] ---
__global__ void quant_rows_t(const float* __restrict__ W, int8_t* __restrict__ D1,
                             int8_t* __restrict__ D2, float* __restrict__ S,
                             int K, int N, long sW, long sT, int sS) {
    int n = blockIdx.x, z = blockIdx.y, t = threadIdx.x;
    W  += (long)z * sW;
    D1 += (long)z * sT;
    D2 += (long)z * sT;
    S  += (long)z * sS;
    int per = K >> 8;
    float v[4], m = 0.f;
    for (int j = 0; j < per; j++) { v[j] = W[(long)(t + j * 256) * N + n]; m = fmaxf(m, fabsf(v[j])); }
    #pragma unroll
    for (int o = 16; o > 0; o >>= 1) m = fmaxf(m, __shfl_xor_sync(0xffffffffu, m, o));
    __shared__ float red[8];
    __shared__ float binv;
    if ((t & 31) == 0) red[t >> 5] = m;
    __syncthreads();
    if (t == 0) {
        float mm = red[0];
        #pragma unroll
        for (int j = 1; j < 8; j++) mm = fmaxf(mm, red[j]);
        mm = fmaxf(mm, 1e-20f);
        binv = 16256.f / mm;
        S[n] = mm * (1.f / 16256.f);
    }
    __syncthreads();
    float inv = binv;
    for (int j = 0; j < per; j++) {
        int8_t d1, d2; quant2(v[j], inv, &d1, &d2);
        D1[(long)n * K + t + j * 256] = d1;
        D2[(long)n * K + t + j * 256] = d2;
    }
}

// ------------------------------- IMMA int8 GEMM ------------------------------
// C[M,N] (op)= (δA δB)·[(128A1+A2)(128B1+B2)^T], dropping A2B2.
// CTA tile 128x64, 128 threads (4 warps, 2x2 grid of 64x32 warp tiles),
// k-chunk 64 int8, 2-stage cp.async. EPI: 0=store, 1=C+=, 2=relu store.
#define TGS     80
#define TGTA    (128 * TGS)               // 10240
#define TGTB    (64 * TGS)                // 5120
#define TGSTAGE (2 * TGTA + 2 * TGTB)     // 30720
#define TG_SMEM (2 * TGSTAGE)             // 61440

template<int EPI>
__global__ void __launch_bounds__(128, 2) tgemm(
    const int8_t* __restrict__ A1, const int8_t* __restrict__ A2,
    const float* __restrict__ sA,
    const int8_t* __restrict__ B1, const int8_t* __restrict__ B2,
    const float* __restrict__ sB,
    float* __restrict__ Cf, int N, int K,
    long strideB, long strideC, int sBstride)
{
    extern __shared__ char smem[];
    const int bn = blockIdx.x, bm = blockIdx.y, bz = blockIdx.z;
    const uint32_t sb = smem_u32(smem);
    int t = threadIdx.x;
    int wid = t >> 5, lane = t & 31;
    int wm = wid & 1, wn = wid >> 1;      // 2 x 2 warp grid

    const int8_t* gsrc[4];
    gsrc[0] = A1 + (long)bm * 128 * K;
    gsrc[1] = A2 + (long)bm * 128 * K;
    gsrc[2] = B1 + (long)bz * strideB + (long)bn * 64 * K;
    gsrc[3] = B2 + (long)bz * strideB + (long)bn * 64 * K;

    int accP[4][4][4], accX[4][4][4];
    #pragma unroll
    for (int i = 0; i < 4; i++)
        #pragma unroll
        for (int j = 0; j < 4; j++)
            #pragma unroll
            for (int r = 0; r < 4; r++) { accP[i][j][r] = 0; accX[i][j][r] = 0; }

    const int nch = K >> 6;

    auto load_chunk = [&](int c, int buf) {
        int k0 = c << 6;
        uint32_t base = sb + buf * TGSTAGE;
        int seg = t & 3, rr = t >> 2;     // rr in [0,32)
        #pragma unroll
        for (int i = 0; i < 12; i++) {
            int tile, r, off;
            if (i < 4)       { tile = 0; r = i * 32 + rr;        off = 0; }
            else if (i < 8)  { tile = 1; r = (i - 4) * 32 + rr;  off = TGTA; }
            else if (i < 10) { tile = 2; r = (i - 8) * 32 + rr;  off = 2 * TGTA; }
            else             { tile = 3; r = (i - 10) * 32 + rr; off = 2 * TGTA + TGTB; }
            uint32_t dst = base + off + r * TGS + seg * 16;
            const int8_t* src = gsrc[tile] + (long)r * K + k0 + seg * 16;
            cp16(dst, src);
        }
        asm volatile("cp.async.commit_group;" ::: "memory");
    };

    load_chunk(0, 0);

    int arow = lane & 15, asel = lane >> 4;
    int brow = (lane & 7) + ((lane >> 4) << 3);
    int bsel = (lane >> 3) & 1;

    for (int c = 0; c < nch; c++) {
        if (c + 1 < nch) {
            load_chunk(c + 1, (c + 1) & 1);
            asm volatile("cp.async.wait_group 1;" ::: "memory");
        } else {
            asm volatile("cp.async.wait_group 0;" ::: "memory");
        }
        __syncthreads();

        uint32_t st = sb + (c & 1) * TGSTAGE;
        uint32_t sA1 = st, sA2 = st + TGTA;
        uint32_t sB1 = st + 2 * TGTA, sB2 = st + 2 * TGTA + TGTB;

        #pragma unroll
        for (int h = 0; h < 2; h++) {
            uint32_t af1[4][4], af2[4][4], bf1[2][4], bf2[2][4];
            #pragma unroll
            for (int mt = 0; mt < 4; mt++)
                ldsm4(af1[mt], sA1 + (wm * 64 + mt * 16 + arow) * TGS + h * 32 + asel * 16);
            #pragma unroll
            for (int bt = 0; bt < 2; bt++)
                ldsm4(bf1[bt], sB1 + (wn * 32 + bt * 16 + brow) * TGS + h * 32 + bsel * 16);
            // pass 0: A1*B1 -> accP
            #pragma unroll
            for (int mt = 0; mt < 4; mt++)
                #pragma unroll
                for (int na = 0; na < 4; na++)
                    imma16832(accP[mt][na], af1[mt], bf1[na >> 1][(na & 1) * 2],
                              bf1[na >> 1][(na & 1) * 2 + 1]);
            // pass 1: A1*B2 -> accX
            #pragma unroll
            for (int bt = 0; bt < 2; bt++)
                ldsm4(bf2[bt], sB2 + (wn * 32 + bt * 16 + brow) * TGS + h * 32 + bsel * 16);
            #pragma unroll
            for (int mt = 0; mt < 4; mt++)
                #pragma unroll
                for (int na = 0; na < 4; na++)
                    imma16832(accX[mt][na], af1[mt], bf2[na >> 1][(na & 1) * 2],
                              bf2[na >> 1][(na & 1) * 2 + 1]);
            // pass 2: A2*B1 -> accX
            #pragma unroll
            for (int mt = 0; mt < 4; mt++)
                ldsm4(af2[mt], sA2 + (wm * 64 + mt * 16 + arow) * TGS + h * 32 + asel * 16);
            #pragma unroll
            for (int mt = 0; mt < 4; mt++)
                #pragma unroll
                for (int na = 0; na < 4; na++)
                    imma16832(accX[mt][na], af2[mt], bf1[na >> 1][(na & 1) * 2],
                              bf1[na >> 1][(na & 1) * 2 + 1]);
        }
        __syncthreads();
    }

    // ------------------------------- epilogue -------------------------------
    int r = lane >> 2, c2 = (lane & 3) * 2;
    const float* sBp = sB + (long)bz * sBstride;
    #pragma unroll
    for (int mt = 0; mt < 4; mt++) {
        int m0 = bm * 128 + wm * 64 + mt * 16;
        float sa0 = sA[m0 + r], sa1 = sA[m0 + r + 8];
        #pragma unroll
        for (int na = 0; na < 4; na++) {
            int nn = bn * 64 + wn * 32 + na * 8 + c2;
            float sb0 = sBp[nn], sb1 = sBp[nn + 1];
            int* P = accP[mt][na];
            int* X = accX[mt][na];
            float v0 = 16384.f * (float)P[0] + 128.f * (float)X[0];
            float v1 = 16384.f * (float)P[1] + 128.f * (float)X[1];
            float v2 = 16384.f * (float)P[2] + 128.f * (float)X[2];
            float v3 = 16384.f * (float)P[3] + 128.f * (float)X[3];
            float c00 = sa0 * sb0 * v0, c01 = sa0 * sb1 * v1;
            float c10 = sa1 * sb0 * v2, c11 = sa1 * sb1 * v3;
            long i0 = (long)bz * strideC + (long)(m0 + r) * N + nn;
            long i1 = (long)bz * strideC + (long)(m0 + r + 8) * N + nn;
            if (EPI == 0) {
                *(float2*)(Cf + i0) = make_float2(c00, c01);
                *(float2*)(Cf + i1) = make_float2(c10, c11);
            } else if (EPI == 1) {
                float2 o0 = *(float2*)(Cf + i0);
                float2 o1 = *(float2*)(Cf + i1);
                o0.x += c00; o0.y += c01; o1.x += c10; o1.y += c11;
                *(float2*)(Cf + i0) = o0;
                *(float2*)(Cf + i1) = o1;
            } else {
                *(float2*)(Cf + i0) = make_float2(fmaxf(c00, 0.f), fmaxf(c01, 0.f));
                *(float2*)(Cf + i1) = make_float2(fmaxf(c10, 0.f), fmaxf(c11, 0.f));
            }
        }
    }
}

// ------------------------------------------ fp32 GEMM (only for wc, 256^3) ---
__global__ void __launch_bounds__(256) sgemm0(const float* __restrict__ A,
                                              const float* __restrict__ B,
                                              float* __restrict__ C,
                                              int M, int N, int K) {
    const int bm = blockIdx.y, bn = blockIdx.x;
    __shared__ float As[2][8][128];
    __shared__ float Bs[2][8][128];
    int t = threadIdx.x;
    int tx = t & 15, ty = t >> 4;
    int arow = t >> 1, acol = (t & 1) * 4;
    int brow = t >> 5, bcol = (t & 31) * 4;
    const float* Ag = A + (bm * 128 + arow) * K + acol;
    const float* Bg = B + brow * N + bn * 128 + bcol;
    float acc[8][8];
    #pragma unroll
    for (int i = 0; i < 8; i++)
        #pragma unroll
        for (int j = 0; j < 8; j++) acc[i][j] = 0.f;
    float4 a4 = *(const float4*)Ag;
    float4 b4 = *(const float4*)Bg;
    As[0][acol + 0][arow] = a4.x; As[0][acol + 1][arow] = a4.y;
    As[0][acol + 2][arow] = a4.z; As[0][acol + 3][arow] = a4.w;
    *(float4*)&Bs[0][brow][bcol] = b4;
    __syncthreads();
    int nk = K >> 3;
    for (int kt = 0; kt < nk; kt++) {
        int cur = kt & 1;
        if (kt + 1 < nk) {
            a4 = *(const float4*)(Ag + (kt + 1) * 8);
            b4 = *(const float4*)(Bg + (kt + 1) * 8 * N);
        }
        #pragma unroll
        for (int kk = 0; kk < 8; kk++) {
            float ar[8], br[8];
            *(float4*)(ar)     = *(const float4*)&As[cur][kk][ty * 8];
            *(float4*)(ar + 4) = *(const float4*)&As[cur][kk][ty * 8 + 4];
            *(float4*)(br)     = *(const float4*)&Bs[cur][kk][tx * 8];
            *(float4*)(br + 4) = *(const float4*)&Bs[cur][kk][tx * 8 + 4];
            #pragma unroll
            for (int i = 0; i < 8; i++)
                #pragma unroll
                for (int j = 0; j < 8; j++) acc[i][j] += ar[i] * br[j];
        }
        if (kt + 1 < nk) {
            int nxt = cur ^ 1;
            As[nxt][acol + 0][arow] = a4.x; As[nxt][acol + 1][arow] = a4.y;
            As[nxt][acol + 2][arow] = a4.z; As[nxt][acol + 3][arow] = a4.w;
            *(float4*)&Bs[nxt][brow][bcol] = b4;
            __syncthreads();
        }
    }
    #pragma unroll
    for (int i = 0; i < 8; i++) {
        float* Cp = C + (bm * 128 + ty * 8 + i) * N + bn * 128 + tx * 8;
        *(float4*)Cp       = make_float4(acc[i][0], acc[i][1], acc[i][2], acc[i][3]);
        *((float4*)Cp + 1) = make_float4(acc[i][4], acc[i][5], acc[i][6], acc[i][7]);
    }
}

// ----------------------- attention (fp32 in, int8 digits out) ----------------
__global__ void attn_kernel(const float* __restrict__ Q,
                            const float* __restrict__ Km,
                            const float* __restrict__ Vm,
                            int8_t* __restrict__ O1, int8_t* __restrict__ O2,
                            float* __restrict__ S, int nq) {
    int seq = blockIdx.x;
    __shared__ float ks[DM * 17];
    __shared__ float vs[KK * DM];
    __shared__ float sc[NH][KK];
    __shared__ float red[8];
    __shared__ float sdelta;
    int t = threadIdx.x;
    for (int i = t; i < KK * DM; i += 256) {
        int j = i >> 8;
        int c = i & 255;
        ks[c * 17 + j] = Km[(seq * KK + j) * DM + c];
        vs[j * DM + c] = Vm[(seq * KK + j) * DM + c];
    }
    __syncthreads();
    int h = t >> 5, lane = t & 31;
    for (int i = 0; i < nq; i++) {
        const float* q = Q + (long)(seq * nq + i) * DM + h * DH;
        float s = -CUDART_INF_F;
        if (lane < KK) {
            float a = 0.f;
            #pragma unroll
            for (int e = 0; e < DH; e++) a += q[e] * ks[(h * DH + e) * 17 + lane];
            s = a * 0.17677669529663687f;
        }
        float m = s;
        #pragma unroll
        for (int o = 16; o > 0; o >>= 1) m = fmaxf(m, __shfl_xor_sync(0xffffffffu, m, o));
        float p = (lane < KK) ? expf(s - m) : 0.f;
        float sum = p;
        #pragma unroll
        for (int o = 16; o > 0; o >>= 1) sum += __shfl_xor_sync(0xffffffffu, sum, o);
        if (lane < KK) sc[h][lane] = p / sum;
        __syncwarp();
        float oa = 0.f;
        #pragma unroll
        for (int j = 0; j < KK; j++) oa += sc[h][j] * vs[j * DM + h * DH + lane];
        // ---- block row-max + quantize ----
        float am = fabsf(oa);
        #pragma unroll
        for (int o = 16; o > 0; o >>= 1) am = fmaxf(am, __shfl_xor_sync(0xffffffffu, am, o));
        if (lane == 0) red[h] = am;
        __syncthreads();
        long row = (long)(seq * nq + i);
        if (t == 0) {
            float mm = red[0];
            #pragma unroll
            for (int j = 1; j < 8; j++) mm = fmaxf(mm, red[j]);
            mm = fmaxf(mm, 1e-20f);
            sdelta = 16256.f / mm;
            S[row] = mm * (1.f / 16256.f);
        }
        __syncthreads();
        float inv = sdelta;
        int8_t d1, d2; quant2(oa, inv, &d1, &d2);
        long oi = row * DM + h * DH + lane;
        O1[oi] = d1;
        O2[oi] = d2;
        __syncthreads();
    }
}

// ------------------------------------------------- final LN + generator ------
__global__ void final_kernel(const float* __restrict__ T,
                             const float* __restrict__ Wg,
                             float* __restrict__ out) {
    int seq = blockIdx.x;
    int t = threadIdx.x;
    __shared__ float y[DM];
    __shared__ float red[DM];
    float v = T[seq * DM + t];
    red[t] = v;
    __syncthreads();
    for (int s = 128; s > 0; s >>= 1) { if (t < s) red[t] += red[t + s]; __syncthreads(); }
    float mean = red[0] * (1.f / 256.f);
    __syncthreads();
    float d = v - mean;
    red[t] = d * d;
    __syncthreads();
    for (int s = 128; s > 0; s >>= 1) { if (t < s) red[t] += red[t + s]; __syncthreads(); }
    float r = rsqrtf(red[0] * (1.f / 256.f) + 1e-6f);
    y[t] = d * r;
    __syncthreads();
    if (t < SEQ) {
        float acc = 0.f;
        for (int dd = 0; dd < DM; dd++) acc += y[dd] * Wg[dd * SEQ + t];
        out[seq * SEQ + t] = acc;
    }
}

// ------------------------------------------------------------------ launch ---
extern "C" void kernel_launch(void* const* d_in, const int* in_sizes, int n_in,
                              void* d_out, int out_size) {
    const float* x_c      = (const float*)d_in[0];
    const float* A        = (const float*)d_in[1];
    const float* Wsrc     = (const float*)d_in[2];
    const float* Wtgt     = (const float*)d_in[3];
    const float* enc_attn = (const float*)d_in[4];
    const float* enc_ffn1 = (const float*)d_in[5];
    const float* enc_ffn2 = (const float*)d_in[6];
    const float* dec_self = (const float*)d_in[7];
    const float* dec_cross= (const float*)d_in[8];
    const float* dec_ffn1 = (const float*)d_in[9];
    const float* dec_ffn2 = (const float*)d_in[10];
    const float* Wgen     = (const float*)d_in[11];
    float* out = (float*)d_out;

    cudaFuncSetAttribute(tgemm<0>, cudaFuncAttributeMaxDynamicSharedMemorySize, TG_SMEM);
    cudaFuncSetAttribute(tgemm<1>, cudaFuncAttributeMaxDynamicSharedMemorySize, TG_SMEM);
    cudaFuncSetAttribute(tgemm<2>, cudaFuncAttributeMaxDynamicSharedMemorySize, TG_SMEM);

    float *src, *qkv, *tgt, *tq, *wc, *hf;  int* idxp;
    cudaGetSymbolAddress((void**)&src, g_src);
    cudaGetSymbolAddress((void**)&qkv, g_qkv);
    cudaGetSymbolAddress((void**)&tgt, g_tgt);
    cudaGetSymbolAddress((void**)&tq,  g_tq);
    cudaGetSymbolAddress((void**)&wc,  g_wc);
    cudaGetSymbolAddress((void**)&hf,  g_hf);
    cudaGetSymbolAddress((void**)&idxp, g_idx);
    int8_t *y1,*y2,*ao1,*ao2,*h1,*h2,*m1,*m2;
    float *sy,*sao,*sh,*sm;
    cudaGetSymbolAddress((void**)&y1, g_y1);   cudaGetSymbolAddress((void**)&y2, g_y2);
    cudaGetSymbolAddress((void**)&ao1, g_ao1); cudaGetSymbolAddress((void**)&ao2, g_ao2);
    cudaGetSymbolAddress((void**)&h1, g_h1);   cudaGetSymbolAddress((void**)&h2, g_h2);
    cudaGetSymbolAddress((void**)&m1, g_m1);   cudaGetSymbolAddress((void**)&m2, g_m2);
    cudaGetSymbolAddress((void**)&sy, g_sy);   cudaGetSymbolAddress((void**)&sao, g_sao);
    cudaGetSymbolAddress((void**)&sh, g_sh);   cudaGetSymbolAddress((void**)&sm, g_sm);
    int8_t *we1,*we2,*wf11,*wf12,*wf21,*wf22,*wx1,*wx2,*wg11,*wg12,*wg21,*wg22,*wc1,*wc2;
    float *swe,*swf1,*swf2,*swx,*swg1,*swg2,*swc;
    cudaGetSymbolAddress((void**)&we1, g_we1);   cudaGetSymbolAddress((void**)&we2, g_we2);
    cudaGetSymbolAddress((void**)&wf11, g_wf11); cudaGetSymbolAddress((void**)&wf12, g_wf12);
    cudaGetSymbolAddress((void**)&wf21, g_wf21); cudaGetSymbolAddress((void**)&wf22, g_wf22);
    cudaGetSymbolAddress((void**)&wx1, g_wx1);   cudaGetSymbolAddress((void**)&wx2, g_wx2);
    cudaGetSymbolAddress((void**)&wg11, g_wg11); cudaGetSymbolAddress((void**)&wg12, g_wg12);
    cudaGetSymbolAddress((void**)&wg21, g_wg21); cudaGetSymbolAddress((void**)&wg22, g_wg22);
    cudaGetSymbolAddress((void**)&wc1, g_wc1);   cudaGetSymbolAddress((void**)&wc2, g_wc2);
    cudaGetSymbolAddress((void**)&swe, g_swe);   cudaGetSymbolAddress((void**)&swf1, g_swf1);
    cudaGetSymbolAddress((void**)&swf2, g_swf2); cudaGetSymbolAddress((void**)&swx, g_swx);
    cudaGetSymbolAddress((void**)&swg1, g_swg1); cudaGetSymbolAddress((void**)&swg2, g_swg2);
    cudaGetSymbolAddress((void**)&swc, g_swc);

    float* q = qkv;
    float* k = qkv + (long)ET * DM;
    float* v = qkv + 2L * ET * DM;

    // ---- weight transpose + quantization ----
    quant_rows_t<<<dim3(DM, 8), 256>>>(enc_attn, we1, we2, swe, DM, DM, DD, DD, DM);
    quant_rows_t<<<dim3(DFF, 2), 256>>>(enc_ffn1, wf11, wf12, swf1, DM, DFF, (long)DM * DFF, (long)DM * DFF, DFF);
    quant_rows_t<<<dim3(DM, 2), 256>>>(enc_ffn2, wf21, wf22, swf2, DFF, DM, (long)DM * DFF, (long)DM * DFF, DM);
    quant_rows_t<<<dim3(DM, 8), 256>>>(dec_cross, wx1, wx2, swx, DM, DM, DD, DD, DM);
    quant_rows_t<<<dim3(DFF, 2), 256>>>(dec_ffn1, wg11, wg12, swg1, DM, DFF, (long)DM * DFF, (long)DM * DFF, DFF);
    quant_rows_t<<<dim3(DM, 2), 256>>>(dec_ffn2, wg21, wg22, swg2, DFF, DM, (long)DM * DFF, (long)DM * DFF, DM);

    topk_kernel<<<NODES, 256>>>(A, idxp);
    embed_src_kernel<<<NT, 256>>>(x_c, idxp, Wsrc, src);
    embed_tgt_kernel<<<NT, 256>>>(x_c, Wtgt, tgt);

    const dim3 gB(4, ET / 128, 1), gBx3(4, ET / 128, 3), gBx2(4, ET / 128, 2), gBF(16, ET / 128, 1);
    const dim3 gS(4, NT / 128, 1), gSF(16, NT / 128, 1);

    // ------------------------------ encoder ------------------------------
    for (int l = 0; l < NL; l++) {
        long wo = (long)l * 4 * DD;
        const float* swl = swe + l * 4 * DM;
        ln_kernel<<<ET / 8, 256>>>(src, y1, y2, sy, ET);
        tgemm<0><<<gBx3, 128, TG_SMEM>>>(y1, y2, sy, we1 + wo, we2 + wo, swl,
                                         q, DM, DM, DD, (long)ET * DM, DM);
        attn_kernel<<<NT, 256>>>(q, k, v, ao1, ao2, sao, KK);
        tgemm<1><<<gB, 128, TG_SMEM>>>(ao1, ao2, sao, we1 + wo + 3 * DD, we2 + wo + 3 * DD,
                                       swl + 3 * DM, src, DM, DM, 0, 0, 0);
        ln_kernel<<<ET / 8, 256>>>(src, y1, y2, sy, ET);
        long f1 = (long)l * DM * DFF;
        tgemm<2><<<gBF, 128, TG_SMEM>>>(y1, y2, sy, wf11 + f1, wf12 + f1, swf1 + l * DFF,
                                        hf, DFF, DM, 0, 0, 0);
        quant_rows<<<ET, 256>>>(hf, h1, h2, sh, DFF);
        tgemm<1><<<gB, 128, TG_SMEM>>>(h1, h2, sh, wf21 + f1, wf22 + f1, swf2 + l * DM,
                                       src, DM, DFF, 0, 0, 0);
    }
    ln_kernel<<<ET / 8, 256>>>(src, m1, m2, sm, ET);

    // ------------------------------ decoder ------------------------------
    for (int l = 0; l < NL; l++) {
        const float* Wd = dec_self + (long)l * 4 * DD;
        long wo = (long)l * 4 * DD;
        long f1 = (long)l * DM * DFF;
        const float* swl = swx + l * 4 * DM;
        // self-attn over 1 token == identity softmax -> tgt += ln(tgt) @ (W2@W3)
        ln_kernel<<<NT / 8, 256>>>(tgt, y1, y2, sy, NT);
        sgemm0<<<dim3(2, 2), 256>>>(Wd + 2 * DD, Wd + 3 * DD, wc, DM, DM, DM);
        quant_rows_t<<<dim3(DM, 1), 256>>>(wc, wc1, wc2, swc, DM, DM, 0, 0, 0);
        tgemm<1><<<gS, 128, TG_SMEM>>>(y1, y2, sy, wc1, wc2, swc, tgt, DM, DM, 0, 0, 0);
        // cross-attn
        ln_kernel<<<NT / 8, 256>>>(tgt, y1, y2, sy, NT);
        tgemm<0><<<gS, 128, TG_SMEM>>>(y1, y2, sy, wx1 + wo, wx2 + wo, swl,
                                       tq, DM, DM, 0, 0, 0);
        tgemm<0><<<gBx2, 128, TG_SMEM>>>(m1, m2, sm, wx1 + wo + DD, wx2 + wo + DD, swl + DM,
                                         k, DM, DM, DD, (long)ET * DM, DM);
        attn_kernel<<<NT, 256>>>(tq, k, v, ao1, ao2, sao, 1);
        tgemm<1><<<gS, 128, TG_SMEM>>>(ao1, ao2, sao, wx1 + wo + 3 * DD, wx2 + wo + 3 * DD,
                                       swl + 3 * DM, tgt, DM, DM, 0, 0, 0);
        // ffn
        ln_kernel<<<NT / 8, 256>>>(tgt, y1, y2, sy, NT);
        tgemm<2><<<gSF, 128, TG_SMEM>>>(y1, y2, sy, wg11 + f1, wg12 + f1, swg1 + l * DFF,
                                        hf, DFF, DM, 0, 0, 0);
        quant_rows<<<NT, 256>>>(hf, h1, h2, sh, DFF);
        tgemm<1><<<gS, 128, TG_SMEM>>>(h1, h2, sh, wg21 + f1, wg22 + f1, swg2 + l * DM,
                                       tgt, DM, DFF, 0, 0, 0);
    }

    final_kernel<<<NT, 256>>>(tgt, Wgen, out);
}